// round 15
// baseline (speedup 1.0000x reference)
#include <cuda_runtime.h>
#include <cuda_bf16.h>
#include <math.h>
#include <stdint.h>

#define T_STEPS 8
#define CH      128
#define PLANE   1024
#define NELEM   (32 * CH * PLANE)          // 4,194,304
#define TOTAL   (T_STEPS * NELEM)          // 33,554,432
#define EPS     1e-5f
#define DELTA   3e-3f                      // IF2 near-threshold flag window
#define FLAGCAP (1 << 21)

// Scratch (no cudaMalloc allowed)
__device__ __align__(16) __nv_bfloat16 g_spk[TOTAL];           // IF1 spikes [p][tb][ci]
__device__ __align__(16) __nv_bfloat16 g_spk2[TOTAL];          // IF2 spikes [p][tb][ci]
__device__ __align__(16) float         g_mid[TOTAL];           // conv1 out [p][tb][co]
__device__ __align__(16) __nv_bfloat16 g_w1p[18 * 128 * 128];  // conv1 2-split [k*2+s][co][ci]
__device__ __align__(16) __nv_bfloat16 g_w2p[18 * 128 * 128];  // conv2 2-split [k*2+s][co][ci]
__device__ unsigned int g_flags[FLAGCAP];
__device__ unsigned int g_nflag;

// ------------------------- helpers -----------------------------------------
__device__ __forceinline__ uint32_t smem_u32(const void* p) {
    uint32_t a;
    asm("{ .reg .u64 t; cvta.to.shared.u64 t, %1; cvt.u32.u64 %0, t; }" : "=r"(a) : "l"(p));
    return a;
}
__device__ __forceinline__ void ldsm4(uint32_t* r, uint32_t a) {
    asm volatile("ldmatrix.sync.aligned.m8n8.x4.shared.b16 {%0,%1,%2,%3}, [%4];"
                 : "=r"(r[0]), "=r"(r[1]), "=r"(r[2]), "=r"(r[3]) : "r"(a));
}
__device__ __forceinline__ void mma16816(float* d, const uint32_t* a, uint32_t b0, uint32_t b1) {
    asm volatile(
        "mma.sync.aligned.m16n8k16.row.col.f32.bf16.bf16.f32 "
        "{%0,%1,%2,%3}, {%4,%5,%6,%7}, {%8,%9}, {%0,%1,%2,%3};"
        : "+f"(d[0]), "+f"(d[1]), "+f"(d[2]), "+f"(d[3])
        : "r"(a[0]), "r"(a[1]), "r"(a[2]), "r"(a[3]), "r"(b0), "r"(b1));
}
// XOR-swizzled offset in a [rows x 128ci] bf16 tile (256B rows, 16B chunks)
__device__ __forceinline__ uint32_t soff(int row, int ch) {
    return (uint32_t)(row * 256 + ((ch ^ (row & 7)) << 4));
}

// ------------------------- weight split (2 bf16 residuals) ------------------
__global__ void wprep_kernel(const float* __restrict__ w, __nv_bfloat16* __restrict__ wp) {
    int idx = blockIdx.x * 256 + threadIdx.x;          // 9*128*128
    if (idx >= 9 * 128 * 128) return;
    int ci = idx & 127, co = (idx >> 7) & 127, k = idx >> 14;
    float v = w[((size_t)co * 128 + ci) * 9 + k];
#pragma unroll
    for (int s = 0; s < 2; s++) {
        __nv_bfloat16 h = __float2bfloat16(v);
        wp[(((size_t)k * 2 + s) * 128 + co) * 128 + ci] = h;
        v -= __bfloat162float(h);
    }
}

// ------------------------- IF1: NCHW fp32 -> [p][tb][ci] bf16 ---------------
__global__ void if1_kernel(const float* __restrict__ x, __nv_bfloat16* __restrict__ out) {
    __shared__ __nv_bfloat16 sm[32][34];
    const int p0 = blockIdx.x * 32, ci0 = blockIdx.y * 32, b = blockIdx.z;
    const int i = threadIdx.x >> 5, j = threadIdx.x & 31;
    const float* xp = x + ((size_t)b * CH + ci0 + i) * PLANE + p0 + j;
    float v = 0.f;
#pragma unroll
    for (int t = 0; t < T_STEPS; t++) {
        v += xp[(size_t)t * NELEM];
        float s = (v >= 1.f) ? 1.f : 0.f;
        v *= (1.f - s);
        __syncthreads();
        sm[j][i] = __float2bfloat16(s);
        __syncthreads();
        out[((size_t)(p0 + i) * 256 + t * 32 + b) * 128 + ci0 + j] = sm[i][j];
    }
}

// ------------------------- IF2 + near-threshold flagging --------------------
__global__ void zero_flag_kernel() {
    if (threadIdx.x == 0 && blockIdx.x == 0) g_nflag = 0;
}
__global__ void if2_flag_kernel(const float* __restrict__ in, __nv_bfloat16* __restrict__ out) {
    size_t idx = (size_t)blockIdx.x * 256 + threadIdx.x;
    int co = (int)(idx & 127);
    int b  = (int)((idx >> 7) & 31);
    size_t p = idx >> 12;
    float v = 0.f;
    bool near = false;
#pragma unroll
    for (int t = 0; t < T_STEPS; t++) {
        size_t off = (p * 256 + (size_t)t * 32 + b) * 128 + co;
        v += in[off];
        near |= (fabsf(v - 1.f) < DELTA);
        float s = (v >= 1.f) ? 1.f : 0.f;
        v *= (1.f - s);
        out[off] = __float2bfloat16(s);
    }
    if (near) {
        unsigned int id = atomicAdd(&g_nflag, 1u);
        if (id < FLAGCAP) g_flags[id] = ((unsigned)p << 12) | ((unsigned)b << 7) | (unsigned)co;
    }
}

// ------------------------- flip correction ----------------------------------
// One warp per flagged neuron; lanes 0-7 recompute conv1+BN (t=lane) in the
// exact FFMA2-reference order (ci ascending, taps row-major), rescan, rewrite.
__global__ void __launch_bounds__(128)
fix_kernel(const __nv_bfloat16* __restrict__ spk, const float* __restrict__ wgt,
           const float* __restrict__ gamma, const float* __restrict__ beta,
           const float* __restrict__ mean,  const float* __restrict__ var,
           __nv_bfloat16* __restrict__ out) {
    const unsigned int n = min(g_nflag, (unsigned)FLAGCAP);
    const int lane = threadIdx.x & 31;
    const int gw = (blockIdx.x * 128 + threadIdx.x) >> 5;
    for (unsigned int i = gw; i < n; i += 4096 * 4) {
        const unsigned int f = g_flags[i];
        const int co = f & 127, b = (f >> 7) & 31, p = f >> 12;
        const int h = p >> 5, w = p & 31;
        float y = 0.f;
        if (lane < 8) {
            const int t = lane;
            float acc = 0.f;
            for (int ci = 0; ci < 128; ci++) {
                const float* wk = wgt + ((size_t)co * 128 + ci) * 9;
#pragma unroll
                for (int ky = 0; ky < 3; ky++) {
                    const int yy = h + ky - 1;
                    if (yy < 0 || yy >= 32) continue;
#pragma unroll
                    for (int kx = 0; kx < 3; kx++) {
                        const int xx = w + kx - 1;
                        if (xx < 0 || xx >= 32) continue;
                        float sp = __bfloat162float(
                            spk[((size_t)(yy * 32 + xx) * 256 + t * 32 + b) * 128 + ci]);
                        acc = fmaf(wk[ky * 3 + kx], sp, acc);
                    }
                }
            }
            const float invd = gamma[co] / sqrtf(var[co] + 1e-5f);
            const float bias = beta[co] - mean[co] * invd;
            y = acc * invd + bias;
        }
        float v = 0.f;
#pragma unroll
        for (int t = 0; t < T_STEPS; t++) {
            float yt = __shfl_sync(0xffffffffu, y, t);
            v += yt;
            float s = (v >= 1.f) ? 1.f : 0.f;
            v *= (1.f - s);
            if (lane == t)
                out[((size_t)p * 256 + t * 32 + b) * 128 + co] = __float2bfloat16(s);
        }
    }
}

// ------------------------- conv 3x3 + BN via mma.sync -----------------------
// Grid (xo=8, y=32, tbq=4), block 256, 1 CTA/SM. 2 weight splits.
// B-centric inner loop: per dy-row all 6 B tiles + 3 A tiles (current split)
// resident in SMEM. Per j-step: 6 A-frags + 12 B-frags -> 96 MMAs (each frag
// loaded once). MODE 0: out [p][tb][co]; MODE 1: NCHW fused transpose.
#define SMEMC (6 * 16384 + 3 * 32768 + 1024)     // 197632
template<int MODE>
__global__ void __launch_bounds__(256, 1)
conv_mma_kernel(const __nv_bfloat16* __restrict__ spk, const __nv_bfloat16* __restrict__ wp,
                const float* __restrict__ gamma, const float* __restrict__ beta,
                const float* __restrict__ mean,  const float* __restrict__ var,
                float* __restrict__ out) {
    extern __shared__ char dsm[];
    const int tid = threadIdx.x, lane = tid & 31, wid = tid >> 5;
    const int x0 = blockIdx.x * 4, y = blockIdx.y, tbq = blockIdx.z;
    const int m0w = (wid & 3) * 32, n0w = (wid >> 2) * 32;

    uint32_t raw = smem_u32(dsm);
    uint32_t sb  = (raw + 1023) & ~1023u;
    char* sp = dsm + (sb - raw);
    char* bP = sp;                     // 6 x 16KB B tiles
    char* aP = sp + 6 * 16384;         // 3 x 32KB A tiles (one per dxi)
    const uint32_t bBu = sb, aBu = sb + 6 * 16384;

    float acc[4][2][4][4];
#pragma unroll
    for (int px = 0; px < 4; px++)
#pragma unroll
        for (int mt = 0; mt < 2; mt++)
#pragma unroll
            for (int nt = 0; nt < 4; nt++)
#pragma unroll
                for (int e = 0; e < 4; e++) acc[px][mt][nt][e] = 0.f;

    // Precomputed fragment addresses (row/col patterns fixed per thread).
    const int aRow0 = m0w + (lane & 15), aColSel = (lane >> 4);
    const int bRow0 = n0w + ((lane >> 4) << 3) + (lane & 7), bColSel = ((lane >> 3) & 1);

    for (int dyi = 0; dyi < 3; dyi++) {
        const int yy = y + dyi - 1;
        if (yy < 0 || yy >= 32) continue;        // uniform across CTA

        __syncthreads();   // prior-iteration reads complete before restage
        // Stage 6 B tiles: source pixels x0-1 .. x0+4, zero-filled when OOB.
#pragma unroll
        for (int bx = 0; bx < 6; bx++) {
            const int xx = x0 + bx - 1;
            char* dst = bP + bx * 16384;
            if (xx >= 0 && xx < 32) {
                const uint4* g = (const uint4*)spk + ((size_t)(yy * 32 + xx) * 256 + tbq * 64) * 16;
#pragma unroll
                for (int ps = 0; ps < 4; ps++) {
                    int vi = ps * 256 + tid;
                    *(uint4*)(dst + soff(vi >> 4, vi & 15)) = __ldg(&g[vi]);
                }
            } else {
#pragma unroll
                for (int ps = 0; ps < 4; ps++) {
                    int vi = ps * 256 + tid;
                    *(uint4*)(dst + soff(vi >> 4, vi & 15)) = make_uint4(0, 0, 0, 0);
                }
            }
        }
        // Stage A tiles for split 0 (3 taps of this dy-row).
#pragma unroll
        for (int dxi = 0; dxi < 3; dxi++) {
            const uint4* g = (const uint4*)wp + (size_t)((dyi * 3 + dxi) * 2) * 2048;
            char* dst = aP + dxi * 32768;
#pragma unroll
            for (int ps = 0; ps < 8; ps++) {
                int vi = ps * 256 + tid;
                *(uint4*)(dst + soff(vi >> 4, vi & 15)) = __ldg(&g[vi]);
            }
        }
        __syncthreads();

#pragma unroll
        for (int s = 0; s < 2; s++) {
            if (s == 1) {
                __syncthreads();   // split-0 reads complete
#pragma unroll
                for (int dxi = 0; dxi < 3; dxi++) {
                    const uint4* g = (const uint4*)wp + (size_t)((dyi * 3 + dxi) * 2 + 1) * 2048;
                    char* dst = aP + dxi * 32768;
#pragma unroll
                    for (int ps = 0; ps < 8; ps++) {
                        int vi = ps * 256 + tid;
                        *(uint4*)(dst + soff(vi >> 4, vi & 15)) = __ldg(&g[vi]);
                    }
                }
                __syncthreads();
            }
#pragma unroll
            for (int j = 0; j < 8; j++) {
                uint32_t a[3][2][4];
#pragma unroll
                for (int dxi = 0; dxi < 3; dxi++)
#pragma unroll
                    for (int mt = 0; mt < 2; mt++)
                        ldsm4(a[dxi][mt], aBu + dxi * 32768
                                          + soff(aRow0 + mt * 16, 2 * j + aColSel));
#pragma unroll
                for (int bxt = 0; bxt < 6; bxt++) {
                    uint32_t b[2][4];
#pragma unroll
                    for (int q = 0; q < 2; q++)
                        ldsm4(b[q], bBu + bxt * 16384
                                    + soff(bRow0 + q * 16, 2 * j + bColSel));
#pragma unroll
                    for (int px = 0; px < 4; px++)
#pragma unroll
                        for (int dxi = 0; dxi < 3; dxi++)
                            if (px + dxi == bxt) {
#pragma unroll
                                for (int mt = 0; mt < 2; mt++)
#pragma unroll
                                    for (int q = 0; q < 2; q++)
#pragma unroll
                                        for (int t = 0; t < 2; t++)
                                            mma16816(acc[px][mt][q * 2 + t], a[dxi][mt],
                                                     b[q][t * 2], b[q][t * 2 + 1]);
                            }
                }
            }
        }
    }

    // Epilogue: BN + store.
    const int lr = lane >> 2, lc = (lane & 3) * 2;
    float iv[2][2], bv[2][2];
#pragma unroll
    for (int mt = 0; mt < 2; mt++)
#pragma unroll
        for (int h = 0; h < 2; h++) {
            int co = m0w + mt * 16 + h * 8 + lr;
            float z = gamma[co] / sqrtf(var[co] + EPS);
            iv[mt][h] = z;
            bv[mt][h] = beta[co] - mean[co] * z;
        }
    if (MODE == 0) {
#pragma unroll
        for (int px = 0; px < 4; px++) {
            float* bas = out + (((size_t)(y * 32 + x0 + px) * 256) + tbq * 64) * 128;
#pragma unroll
            for (int mt = 0; mt < 2; mt++) {
                const int co = m0w + mt * 16 + lr;
#pragma unroll
                for (int nt = 0; nt < 4; nt++) {
                    const int n = n0w + nt * 8 + lc;
                    float* o = bas + (size_t)n * 128 + co;
                    o[0]   = acc[px][mt][nt][0] * iv[mt][0] + bv[mt][0];
                    o[128] = acc[px][mt][nt][1] * iv[mt][0] + bv[mt][0];
                    o[8]   = acc[px][mt][nt][2] * iv[mt][1] + bv[mt][1];
                    o[136] = acc[px][mt][nt][3] * iv[mt][1] + bv[mt][1];
                }
            }
        }
    } else {
        // NCHW: out[(tb*128+co)*1024 + y*32 + x], float4 over px (x0 % 4 == 0).
        const int pbase = y * 32 + x0;
#pragma unroll
        for (int mt = 0; mt < 2; mt++) {
            const int co = m0w + mt * 16 + lr;
#pragma unroll
            for (int nt = 0; nt < 4; nt++) {
                const int n = tbq * 64 + n0w + nt * 8 + lc;
#pragma unroll
                for (int e = 0; e < 4; e++) {
                    const int cc = co + (e >> 1) * 8;
                    const int nn = n + (e & 1);
                    const float z = iv[mt][e >> 1], bb = bv[mt][e >> 1];
                    float4 v = make_float4(acc[0][mt][nt][e] * z + bb,
                                           acc[1][mt][nt][e] * z + bb,
                                           acc[2][mt][nt][e] * z + bb,
                                           acc[3][mt][nt][e] * z + bb);
                    *(float4*)(out + ((size_t)nn * 128 + cc) * 1024 + pbase) = v;
                }
            }
        }
    }
}

// ------------------------- pipeline -----------------------------------------
extern "C" void kernel_launch(void* const* d_in, const int* in_sizes, int n_in,
                              void* d_out, int out_size) {
    const float* x  = (const float*)d_in[0];
    const float* w1 = (const float*)d_in[1];
    const float* g1 = (const float*)d_in[2];
    const float* b1 = (const float*)d_in[3];
    const float* m1 = (const float*)d_in[4];
    const float* v1 = (const float*)d_in[5];
    const float* w2 = (const float*)d_in[6];
    const float* g2 = (const float*)d_in[7];
    const float* b2 = (const float*)d_in[8];
    const float* m2 = (const float*)d_in[9];
    const float* v2 = (const float*)d_in[10];
    float* out = (float*)d_out;

    __nv_bfloat16 *spk, *spk2, *w1p, *w2p; float* mid;
    cudaGetSymbolAddress((void**)&spk,  g_spk);
    cudaGetSymbolAddress((void**)&spk2, g_spk2);
    cudaGetSymbolAddress((void**)&mid,  g_mid);
    cudaGetSymbolAddress((void**)&w1p,  g_w1p);
    cudaGetSymbolAddress((void**)&w2p,  g_w2p);

    cudaFuncSetAttribute(conv_mma_kernel<0>, cudaFuncAttributeMaxDynamicSharedMemorySize, SMEMC);
    cudaFuncSetAttribute(conv_mma_kernel<1>, cudaFuncAttributeMaxDynamicSharedMemorySize, SMEMC);

    wprep_kernel<<<(9 * 128 * 128 + 255) / 256, 256>>>(w1, w1p);
    wprep_kernel<<<(9 * 128 * 128 + 255) / 256, 256>>>(w2, w2p);
    zero_flag_kernel<<<1, 32>>>();

    if1_kernel<<<dim3(32, 4, 32), 1024>>>(x, spk);

    dim3 cgrid(8, 32, 4);
    conv_mma_kernel<0><<<cgrid, 256, SMEMC>>>(spk, w1p, g1, b1, m1, v1, mid);
    if2_flag_kernel<<<NELEM / 256, 256>>>(mid, spk2);
    fix_kernel<<<4096, 128>>>(spk, w1, g1, b1, m1, v1, spk2);
    conv_mma_kernel<1><<<cgrid, 256, SMEMC>>>(spk2, w2p, g2, b2, m2, v2, out);
}

// round 16
// speedup vs baseline: 1.3829x; 1.3829x over previous
#include <cuda_runtime.h>
#include <cuda_fp16.h>
#include <math.h>
#include <stdint.h>

#define T_STEPS 8
#define CH      128
#define PLANE   1024
#define NELEM   (32 * CH * PLANE)          // 4,194,304
#define TOTAL   (T_STEPS * NELEM)          // 33,554,432
#define EPS     1e-5f
#define DELTA   4e-3f                      // IF2 near-threshold flag window
#define FLAGCAP (1 << 21)

// Scratch (no cudaMalloc allowed)
__device__ __align__(16) __half g_spk[TOTAL];            // IF1 spikes [p][tb][ci]
__device__ __align__(16) __half g_spk2[TOTAL];           // IF2 spikes [p][tb][ci]
__device__ __align__(16) float  g_mid[TOTAL];            // conv1 out [p][tb][co]
__device__ __align__(16) __half g_w1p[9 * 128 * 128];    // conv1 fp16 [k][co][ci]
__device__ __align__(16) __half g_w2p[9 * 128 * 128];    // conv2 fp16 [k][co][ci]
__device__ unsigned int g_flags[FLAGCAP];
__device__ unsigned int g_nflag;

// ------------------------- helpers -----------------------------------------
__device__ __forceinline__ uint32_t smem_u32(const void* p) {
    uint32_t a;
    asm("{ .reg .u64 t; cvta.to.shared.u64 t, %1; cvt.u32.u64 %0, t; }" : "=r"(a) : "l"(p));
    return a;
}
__device__ __forceinline__ void ldsm4(uint32_t* r, uint32_t a) {
    asm volatile("ldmatrix.sync.aligned.m8n8.x4.shared.b16 {%0,%1,%2,%3}, [%4];"
                 : "=r"(r[0]), "=r"(r[1]), "=r"(r[2]), "=r"(r[3]) : "r"(a));
}
__device__ __forceinline__ void mma16816(float* d, const uint32_t* a, uint32_t b0, uint32_t b1) {
    asm volatile(
        "mma.sync.aligned.m16n8k16.row.col.f32.f16.f16.f32 "
        "{%0,%1,%2,%3}, {%4,%5,%6,%7}, {%8,%9}, {%0,%1,%2,%3};"
        : "+f"(d[0]), "+f"(d[1]), "+f"(d[2]), "+f"(d[3])
        : "r"(a[0]), "r"(a[1]), "r"(a[2]), "r"(a[3]), "r"(b0), "r"(b1));
}
// XOR-swizzled offset in a [rows x 128ci] 16-bit tile (256B rows, 16B chunks)
__device__ __forceinline__ uint32_t soff(int row, int ch) {
    return (uint32_t)(row * 256 + ((ch ^ (row & 7)) << 4));
}

// ------------------------- weight prep (single fp16) ------------------------
__global__ void wprep_kernel(const float* __restrict__ w, __half* __restrict__ wp) {
    int idx = blockIdx.x * 256 + threadIdx.x;          // 9*128*128
    if (idx >= 9 * 128 * 128) return;
    int ci = idx & 127, co = (idx >> 7) & 127, k = idx >> 14;
    wp[((size_t)k * 128 + co) * 128 + ci] = __float2half(w[((size_t)co * 128 + ci) * 9 + k]);
}

// ------------------------- IF1: NCHW fp32 -> [p][tb][ci] fp16 ---------------
__global__ void if1_kernel(const float* __restrict__ x, __half* __restrict__ out) {
    __shared__ __half sm[32][34];
    const int p0 = blockIdx.x * 32, ci0 = blockIdx.y * 32, b = blockIdx.z;
    const int i = threadIdx.x >> 5, j = threadIdx.x & 31;
    const float* xp = x + ((size_t)b * CH + ci0 + i) * PLANE + p0 + j;
    float v = 0.f;
#pragma unroll
    for (int t = 0; t < T_STEPS; t++) {
        v += xp[(size_t)t * NELEM];
        float s = (v >= 1.f) ? 1.f : 0.f;
        v *= (1.f - s);
        __syncthreads();
        sm[j][i] = __float2half(s);
        __syncthreads();
        out[((size_t)(p0 + i) * 256 + t * 32 + b) * 128 + ci0 + j] = sm[i][j];
    }
}

// ------------------------- IF2 + near-threshold flagging --------------------
__global__ void zero_flag_kernel() {
    if (threadIdx.x == 0 && blockIdx.x == 0) g_nflag = 0;
}
__global__ void if2_flag_kernel(const float* __restrict__ in, __half* __restrict__ out) {
    size_t idx = (size_t)blockIdx.x * 256 + threadIdx.x;
    int co = (int)(idx & 127);
    int b  = (int)((idx >> 7) & 31);
    size_t p = idx >> 12;
    float v = 0.f;
    bool near = false;
#pragma unroll
    for (int t = 0; t < T_STEPS; t++) {
        size_t off = (p * 256 + (size_t)t * 32 + b) * 128 + co;
        v += in[off];
        near |= (fabsf(v - 1.f) < DELTA);
        float s = (v >= 1.f) ? 1.f : 0.f;
        v *= (1.f - s);
        out[off] = __float2half(s);
    }
    if (near) {
        unsigned int id = atomicAdd(&g_nflag, 1u);
        if (id < FLAGCAP) g_flags[id] = ((unsigned)p << 12) | ((unsigned)b << 7) | (unsigned)co;
    }
}

// ------------------------- flip correction (32-lane parallel) ---------------
// One warp per flagged neuron. lane = t*4 + cq: lane accumulates 32 ci
// (cq*32..) over 9 taps in fp32 using ORIGINAL fp32 weights; butterfly-reduce
// over cq; BN; sequential 8-step rescan; rewrite the 8 spikes.
__global__ void __launch_bounds__(128)
fix_kernel(const __half* __restrict__ spk, const float* __restrict__ wgt,
           const float* __restrict__ gamma, const float* __restrict__ beta,
           const float* __restrict__ mean,  const float* __restrict__ var,
           __half* __restrict__ out) {
    const unsigned int n = min(g_nflag, (unsigned)FLAGCAP);
    const int lane = threadIdx.x & 31;
    const int t  = lane >> 2;          // timestep 0..7
    const int cq = lane & 3;           // ci quarter
    const int gw = (blockIdx.x * 128 + threadIdx.x) >> 5;
    const int nw = gridDim.x * 4;
    for (unsigned int i = gw; i < n; i += nw) {
        const unsigned int f = g_flags[i];
        const int co = f & 127, b = (f >> 7) & 31, p = f >> 12;
        const int h = p >> 5, w = p & 31;
        float acc = 0.f;
#pragma unroll
        for (int ky = 0; ky < 3; ky++) {
            const int yy = h + ky - 1;
            if (yy < 0 || yy >= 32) continue;
#pragma unroll
            for (int kx = 0; kx < 3; kx++) {
                const int xx = w + kx - 1;
                if (xx < 0 || xx >= 32) continue;
                const __half* sb = spk + ((size_t)(yy * 32 + xx) * 256 + t * 32 + b) * 128 + cq * 32;
                const float* wb = wgt + ((size_t)co * 128 + cq * 32) * 9 + ky * 3 + kx;
#pragma unroll 8
                for (int ci = 0; ci < 32; ci++)
                    acc = fmaf(wb[ci * 9], __half2float(sb[ci]), acc);
            }
        }
        acc += __shfl_xor_sync(0xffffffffu, acc, 1);
        acc += __shfl_xor_sync(0xffffffffu, acc, 2);
        const float invd = gamma[co] / sqrtf(var[co] + 1e-5f);
        const float bias = beta[co] - mean[co] * invd;
        const float y = acc * invd + bias;     // lanes of same t agree
        float v = 0.f;
#pragma unroll
        for (int t2 = 0; t2 < T_STEPS; t2++) {
            float yt = __shfl_sync(0xffffffffu, y, t2 * 4);
            v += yt;
            float s = (v >= 1.f) ? 1.f : 0.f;
            v *= (1.f - s);
            if (lane == t2)
                out[((size_t)p * 256 + t2 * 32 + b) * 128 + co] = __float2half(s);
        }
    }
}

// ------------------------- conv 3x3 + BN via mma.sync (fp16, 1 split) -------
// Grid (xo=8, y=32, tbq=4), block 256, 1 CTA/SM.
// Per dy-row: 6 B tiles + 3 A tiles resident; per j-step 6 A-frags + 12
// B-frags -> 96 MMAs. MODE 0: out [p][tb][co]; MODE 1: NCHW fused transpose.
#define SMEMC (6 * 16384 + 3 * 32768 + 1024)     // 197632
template<int MODE>
__global__ void __launch_bounds__(256, 1)
conv_mma_kernel(const __half* __restrict__ spk, const __half* __restrict__ wp,
                const float* __restrict__ gamma, const float* __restrict__ beta,
                const float* __restrict__ mean,  const float* __restrict__ var,
                float* __restrict__ out) {
    extern __shared__ char dsm[];
    const int tid = threadIdx.x, lane = tid & 31, wid = tid >> 5;
    const int x0 = blockIdx.x * 4, y = blockIdx.y, tbq = blockIdx.z;
    const int m0w = (wid & 3) * 32, n0w = (wid >> 2) * 32;

    uint32_t raw = smem_u32(dsm);
    uint32_t sb  = (raw + 1023) & ~1023u;
    char* sp = dsm + (sb - raw);
    char* bP = sp;                     // 6 x 16KB B tiles
    char* aP = sp + 6 * 16384;         // 3 x 32KB A tiles (one per dxi)
    const uint32_t bBu = sb, aBu = sb + 6 * 16384;

    float acc[4][2][4][4];
#pragma unroll
    for (int px = 0; px < 4; px++)
#pragma unroll
        for (int mt = 0; mt < 2; mt++)
#pragma unroll
            for (int nt = 0; nt < 4; nt++)
#pragma unroll
                for (int e = 0; e < 4; e++) acc[px][mt][nt][e] = 0.f;

    const int aRow0 = m0w + (lane & 15), aColSel = (lane >> 4);
    const int bRow0 = n0w + ((lane >> 4) << 3) + (lane & 7), bColSel = ((lane >> 3) & 1);

    for (int dyi = 0; dyi < 3; dyi++) {
        const int yy = y + dyi - 1;
        if (yy < 0 || yy >= 32) continue;        // uniform across CTA

        __syncthreads();   // prior-iteration reads complete before restage
        // Stage 6 B tiles: source pixels x0-1 .. x0+4, zero-filled when OOB.
#pragma unroll
        for (int bx = 0; bx < 6; bx++) {
            const int xx = x0 + bx - 1;
            char* dst = bP + bx * 16384;
            if (xx >= 0 && xx < 32) {
                const uint4* g = (const uint4*)spk + ((size_t)(yy * 32 + xx) * 256 + tbq * 64) * 16;
#pragma unroll
                for (int ps = 0; ps < 4; ps++) {
                    int vi = ps * 256 + tid;
                    *(uint4*)(dst + soff(vi >> 4, vi & 15)) = __ldg(&g[vi]);
                }
            } else {
#pragma unroll
                for (int ps = 0; ps < 4; ps++) {
                    int vi = ps * 256 + tid;
                    *(uint4*)(dst + soff(vi >> 4, vi & 15)) = make_uint4(0, 0, 0, 0);
                }
            }
        }
        // Stage 3 A tiles (taps of this dy-row), single fp16 split.
#pragma unroll
        for (int dxi = 0; dxi < 3; dxi++) {
            const uint4* g = (const uint4*)wp + (size_t)(dyi * 3 + dxi) * 2048;
            char* dst = aP + dxi * 32768;
#pragma unroll
            for (int ps = 0; ps < 8; ps++) {
                int vi = ps * 256 + tid;
                *(uint4*)(dst + soff(vi >> 4, vi & 15)) = __ldg(&g[vi]);
            }
        }
        __syncthreads();

#pragma unroll
        for (int j = 0; j < 8; j++) {
            uint32_t a[3][2][4];
#pragma unroll
            for (int dxi = 0; dxi < 3; dxi++)
#pragma unroll
                for (int mt = 0; mt < 2; mt++)
                    ldsm4(a[dxi][mt], aBu + dxi * 32768
                                      + soff(aRow0 + mt * 16, 2 * j + aColSel));
#pragma unroll
            for (int bxt = 0; bxt < 6; bxt++) {
                uint32_t b[2][4];
#pragma unroll
                for (int q = 0; q < 2; q++)
                    ldsm4(b[q], bBu + bxt * 16384
                                + soff(bRow0 + q * 16, 2 * j + bColSel));
#pragma unroll
                for (int px = 0; px < 4; px++)
#pragma unroll
                    for (int dxi = 0; dxi < 3; dxi++)
                        if (px + dxi == bxt) {
#pragma unroll
                            for (int mt = 0; mt < 2; mt++)
#pragma unroll
                                for (int q = 0; q < 2; q++)
#pragma unroll
                                    for (int t = 0; t < 2; t++)
                                        mma16816(acc[px][mt][q * 2 + t], a[dxi][mt],
                                                 b[q][t * 2], b[q][t * 2 + 1]);
                        }
            }
        }
    }

    // Epilogue: BN + store.
    const int lr = lane >> 2, lc = (lane & 3) * 2;
    float iv[2][2], bv[2][2];
#pragma unroll
    for (int mt = 0; mt < 2; mt++)
#pragma unroll
        for (int h = 0; h < 2; h++) {
            int co = m0w + mt * 16 + h * 8 + lr;
            float z = gamma[co] / sqrtf(var[co] + EPS);
            iv[mt][h] = z;
            bv[mt][h] = beta[co] - mean[co] * z;
        }
    if (MODE == 0) {
#pragma unroll
        for (int px = 0; px < 4; px++) {
            float* bas = out + (((size_t)(y * 32 + x0 + px) * 256) + tbq * 64) * 128;
#pragma unroll
            for (int mt = 0; mt < 2; mt++) {
                const int co = m0w + mt * 16 + lr;
#pragma unroll
                for (int nt = 0; nt < 4; nt++) {
                    const int n = n0w + nt * 8 + lc;
                    float* o = bas + (size_t)n * 128 + co;
                    o[0]   = acc[px][mt][nt][0] * iv[mt][0] + bv[mt][0];
                    o[128] = acc[px][mt][nt][1] * iv[mt][0] + bv[mt][0];
                    o[8]   = acc[px][mt][nt][2] * iv[mt][1] + bv[mt][1];
                    o[136] = acc[px][mt][nt][3] * iv[mt][1] + bv[mt][1];
                }
            }
        }
    } else {
        // NCHW: out[(tb*128+co)*1024 + y*32 + x], float4 over px (x0 % 4 == 0).
        const int pbase = y * 32 + x0;
#pragma unroll
        for (int mt = 0; mt < 2; mt++) {
            const int co = m0w + mt * 16 + lr;
#pragma unroll
            for (int nt = 0; nt < 4; nt++) {
                const int n = tbq * 64 + n0w + nt * 8 + lc;
#pragma unroll
                for (int e = 0; e < 4; e++) {
                    const int cc = co + (e >> 1) * 8;
                    const int nn = n + (e & 1);
                    const float z = iv[mt][e >> 1], bb = bv[mt][e >> 1];
                    float4 v = make_float4(acc[0][mt][nt][e] * z + bb,
                                           acc[1][mt][nt][e] * z + bb,
                                           acc[2][mt][nt][e] * z + bb,
                                           acc[3][mt][nt][e] * z + bb);
                    *(float4*)(out + ((size_t)nn * 128 + cc) * 1024 + pbase) = v;
                }
            }
        }
    }
}

// ------------------------- pipeline -----------------------------------------
extern "C" void kernel_launch(void* const* d_in, const int* in_sizes, int n_in,
                              void* d_out, int out_size) {
    const float* x  = (const float*)d_in[0];
    const float* w1 = (const float*)d_in[1];
    const float* g1 = (const float*)d_in[2];
    const float* b1 = (const float*)d_in[3];
    const float* m1 = (const float*)d_in[4];
    const float* v1 = (const float*)d_in[5];
    const float* w2 = (const float*)d_in[6];
    const float* g2 = (const float*)d_in[7];
    const float* b2 = (const float*)d_in[8];
    const float* m2 = (const float*)d_in[9];
    const float* v2 = (const float*)d_in[10];
    float* out = (float*)d_out;

    __half *spk, *spk2, *w1p, *w2p; float* mid;
    cudaGetSymbolAddress((void**)&spk,  g_spk);
    cudaGetSymbolAddress((void**)&spk2, g_spk2);
    cudaGetSymbolAddress((void**)&mid,  g_mid);
    cudaGetSymbolAddress((void**)&w1p,  g_w1p);
    cudaGetSymbolAddress((void**)&w2p,  g_w2p);

    cudaFuncSetAttribute(conv_mma_kernel<0>, cudaFuncAttributeMaxDynamicSharedMemorySize, SMEMC);
    cudaFuncSetAttribute(conv_mma_kernel<1>, cudaFuncAttributeMaxDynamicSharedMemorySize, SMEMC);

    wprep_kernel<<<(9 * 128 * 128 + 255) / 256, 256>>>(w1, w1p);
    wprep_kernel<<<(9 * 128 * 128 + 255) / 256, 256>>>(w2, w2p);
    zero_flag_kernel<<<1, 32>>>();

    if1_kernel<<<dim3(32, 4, 32), 1024>>>(x, spk);

    dim3 cgrid(8, 32, 4);
    conv_mma_kernel<0><<<cgrid, 256, SMEMC>>>(spk, w1p, g1, b1, m1, v1, mid);
    if2_flag_kernel<<<NELEM / 256, 256>>>(mid, spk2);
    fix_kernel<<<2048, 128>>>(spk, w1, g1, b1, m1, v1, spk2);
    conv_mma_kernel<1><<<cgrid, 256, SMEMC>>>(spk2, w2p, g2, b2, m2, v2, out);
}

// round 17
// speedup vs baseline: 2.4515x; 1.7727x over previous
#include <cuda_runtime.h>
#include <cuda_fp16.h>
#include <math.h>
#include <stdint.h>

#define T_STEPS 8
#define CH      128
#define PLANE   1024
#define NELEM   (32 * CH * PLANE)          // 4,194,304
#define TOTAL   (T_STEPS * NELEM)          // 33,554,432
#define EPS     1e-5f
#define DELTA   4e-3f                      // IF2 near-threshold flag window
#define FLAGCAP (1 << 21)

// Scratch (no cudaMalloc allowed)
__device__ __align__(16) __half g_spk[TOTAL];            // IF1 spikes [p][tb][ci]
__device__ __align__(16) __half g_spk2[TOTAL];           // IF2 spikes [p][tb][ci]
__device__ __align__(16) float  g_mid[TOTAL];            // conv1 out [p][tb][co]
__device__ __align__(16) __half g_w1p[9 * 128 * 128];    // conv1 fp16 [k][co][ci]
__device__ __align__(16) __half g_w2p[9 * 128 * 128];    // conv2 fp16 [k][co][ci]
__device__ __align__(16) float  g_w1t[9 * 128 * 128];    // conv1 fp32 [k][co][ci] (for fix)
__device__ unsigned int g_flags[FLAGCAP];
__device__ unsigned int g_nflag;

// ------------------------- helpers -----------------------------------------
__device__ __forceinline__ uint32_t smem_u32(const void* p) {
    uint32_t a;
    asm("{ .reg .u64 t; cvta.to.shared.u64 t, %1; cvt.u32.u64 %0, t; }" : "=r"(a) : "l"(p));
    return a;
}
__device__ __forceinline__ void ldsm4(uint32_t* r, uint32_t a) {
    asm volatile("ldmatrix.sync.aligned.m8n8.x4.shared.b16 {%0,%1,%2,%3}, [%4];"
                 : "=r"(r[0]), "=r"(r[1]), "=r"(r[2]), "=r"(r[3]) : "r"(a));
}
__device__ __forceinline__ void mma16816(float* d, const uint32_t* a, uint32_t b0, uint32_t b1) {
    asm volatile(
        "mma.sync.aligned.m16n8k16.row.col.f32.f16.f16.f32 "
        "{%0,%1,%2,%3}, {%4,%5,%6,%7}, {%8,%9}, {%0,%1,%2,%3};"
        : "+f"(d[0]), "+f"(d[1]), "+f"(d[2]), "+f"(d[3])
        : "r"(a[0]), "r"(a[1]), "r"(a[2]), "r"(a[3]), "r"(b0), "r"(b1));
}
// XOR-swizzled offset in a [rows x 128ci] 16-bit tile (256B rows, 16B chunks)
__device__ __forceinline__ uint32_t soff(int row, int ch) {
    return (uint32_t)(row * 256 + ((ch ^ (row & 7)) << 4));
}

// ------------------------- weight prep --------------------------------------
// fp16 [k][co][ci] for MMA; optionally fp32 transposed copy for fix_kernel.
template<bool WT>
__global__ void wprep_kernel(const float* __restrict__ w, __half* __restrict__ wp,
                             float* __restrict__ wt) {
    int idx = blockIdx.x * 256 + threadIdx.x;          // 9*128*128
    if (idx >= 9 * 128 * 128) return;
    int ci = idx & 127, co = (idx >> 7) & 127, k = idx >> 14;
    float v = w[((size_t)co * 128 + ci) * 9 + k];
    wp[((size_t)k * 128 + co) * 128 + ci] = __float2half(v);
    if (WT) wt[((size_t)k * 128 + co) * 128 + ci] = v;
}

// ------------------------- IF1: NCHW fp32 -> [p][tb][ci] fp16 ---------------
__global__ void if1_kernel(const float* __restrict__ x, __half* __restrict__ out) {
    __shared__ __half sm[32][34];
    const int p0 = blockIdx.x * 32, ci0 = blockIdx.y * 32, b = blockIdx.z;
    const int i = threadIdx.x >> 5, j = threadIdx.x & 31;
    const float* xp = x + ((size_t)b * CH + ci0 + i) * PLANE + p0 + j;
    float v = 0.f;
#pragma unroll
    for (int t = 0; t < T_STEPS; t++) {
        v += xp[(size_t)t * NELEM];
        float s = (v >= 1.f) ? 1.f : 0.f;
        v *= (1.f - s);
        __syncthreads();
        sm[j][i] = __float2half(s);
        __syncthreads();
        out[((size_t)(p0 + i) * 256 + t * 32 + b) * 128 + ci0 + j] = sm[i][j];
    }
}

// ------------------------- IF2 + near-threshold flagging --------------------
__global__ void zero_flag_kernel() {
    if (threadIdx.x == 0 && blockIdx.x == 0) g_nflag = 0;
}
__global__ void if2_flag_kernel(const float* __restrict__ in, __half* __restrict__ out) {
    size_t idx = (size_t)blockIdx.x * 256 + threadIdx.x;
    int co = (int)(idx & 127);
    int b  = (int)((idx >> 7) & 31);
    size_t p = idx >> 12;
    float v = 0.f;
    bool near = false;
#pragma unroll
    for (int t = 0; t < T_STEPS; t++) {
        size_t off = (p * 256 + (size_t)t * 32 + b) * 128 + co;
        v += in[off];
        near |= (fabsf(v - 1.f) < DELTA);
        float s = (v >= 1.f) ? 1.f : 0.f;
        v *= (1.f - s);
        out[off] = __float2half(s);
    }
    if (near) {
        unsigned int id = atomicAdd(&g_nflag, 1u);
        if (id < FLAGCAP) g_flags[id] = ((unsigned)p << 12) | ((unsigned)b << 7) | (unsigned)co;
    }
}

// ------------------------- flip correction (vectorized) ---------------------
// One warp per flagged neuron. lane = t*4 + cq: lane accumulates ci range
// [cq*32, cq*32+32) over 9 taps in fp32 using transposed fp32 weights
// (contiguous float4 loads); butterfly-reduce over cq; BN; 8-step rescan.
__global__ void __launch_bounds__(128)
fix_kernel(const __half* __restrict__ spk, const float* __restrict__ w1t,
           const float* __restrict__ gamma, const float* __restrict__ beta,
           const float* __restrict__ mean,  const float* __restrict__ var,
           __half* __restrict__ out) {
    const unsigned int n = min(g_nflag, (unsigned)FLAGCAP);
    const int lane = threadIdx.x & 31;
    const int t  = lane >> 2;          // timestep 0..7
    const int cq = lane & 3;           // ci quarter
    const int gw = (blockIdx.x * 128 + threadIdx.x) >> 5;
    const int nw = gridDim.x * 4;
    for (unsigned int i = gw; i < n; i += nw) {
        const unsigned int f = g_flags[i];
        const int co = f & 127, b = (f >> 7) & 31, p = f >> 12;
        const int h = p >> 5, w = p & 31;
        float acc = 0.f;
#pragma unroll
        for (int ky = 0; ky < 3; ky++) {
            const int yy = h + ky - 1;
            if (yy < 0 || yy >= 32) continue;
#pragma unroll
            for (int kx = 0; kx < 3; kx++) {
                const int xx = w + kx - 1;
                if (xx < 0 || xx >= 32) continue;
                const int k = ky * 3 + kx;
                const float4* wv = (const float4*)(w1t + ((size_t)k * 128 + co) * 128 + cq * 32);
                const float4* sv = (const float4*)(spk + ((size_t)(yy * 32 + xx) * 256 + t * 32 + b) * 128 + cq * 32);
#pragma unroll
                for (int v4 = 0; v4 < 4; v4++) {
                    float4 s4 = __ldg(&sv[v4]);
                    float4 w0 = __ldg(&wv[v4 * 2]);
                    float4 w1 = __ldg(&wv[v4 * 2 + 1]);
                    const __half2* hh = (const __half2*)&s4;
                    float2 f0 = __half22float2(hh[0]), f1 = __half22float2(hh[1]);
                    float2 f2 = __half22float2(hh[2]), f3 = __half22float2(hh[3]);
                    acc = fmaf(w0.x, f0.x, acc); acc = fmaf(w0.y, f0.y, acc);
                    acc = fmaf(w0.z, f1.x, acc); acc = fmaf(w0.w, f1.y, acc);
                    acc = fmaf(w1.x, f2.x, acc); acc = fmaf(w1.y, f2.y, acc);
                    acc = fmaf(w1.z, f3.x, acc); acc = fmaf(w1.w, f3.y, acc);
                }
            }
        }
        acc += __shfl_xor_sync(0xffffffffu, acc, 1);
        acc += __shfl_xor_sync(0xffffffffu, acc, 2);
        const float invd = gamma[co] / sqrtf(var[co] + 1e-5f);
        const float bias = beta[co] - mean[co] * invd;
        const float y = acc * invd + bias;     // lanes of same t agree
        float v = 0.f;
#pragma unroll
        for (int t2 = 0; t2 < T_STEPS; t2++) {
            float yt = __shfl_sync(0xffffffffu, y, t2 * 4);
            v += yt;
            float s = (v >= 1.f) ? 1.f : 0.f;
            v *= (1.f - s);
            if (lane == t2)
                out[((size_t)p * 256 + t2 * 32 + b) * 128 + co] = __float2half(s);
        }
    }
}

// ------------------------- conv 3x3 + BN via mma.sync (fp16, 1 split) -------
// Grid (xo=8, y=32, tbq=4), block 256, 1 CTA/SM.
// Per dy-row: 6 B tiles + 3 A tiles resident; per j-step 6 A-frags + 12
// B-frags -> 96 MMAs. MODE 0: out [p][tb][co]; MODE 1: NCHW fused transpose.
#define SMEMC (6 * 16384 + 3 * 32768 + 1024)     // 197632
template<int MODE>
__global__ void __launch_bounds__(256, 1)
conv_mma_kernel(const __half* __restrict__ spk, const __half* __restrict__ wp,
                const float* __restrict__ gamma, const float* __restrict__ beta,
                const float* __restrict__ mean,  const float* __restrict__ var,
                float* __restrict__ out) {
    extern __shared__ char dsm[];
    const int tid = threadIdx.x, lane = tid & 31, wid = tid >> 5;
    const int x0 = blockIdx.x * 4, y = blockIdx.y, tbq = blockIdx.z;
    const int m0w = (wid & 3) * 32, n0w = (wid >> 2) * 32;

    uint32_t raw = smem_u32(dsm);
    uint32_t sb  = (raw + 1023) & ~1023u;
    char* sp = dsm + (sb - raw);
    char* bP = sp;                     // 6 x 16KB B tiles
    char* aP = sp + 6 * 16384;         // 3 x 32KB A tiles (one per dxi)
    const uint32_t bBu = sb, aBu = sb + 6 * 16384;

    float acc[4][2][4][4];
#pragma unroll
    for (int px = 0; px < 4; px++)
#pragma unroll
        for (int mt = 0; mt < 2; mt++)
#pragma unroll
            for (int nt = 0; nt < 4; nt++)
#pragma unroll
                for (int e = 0; e < 4; e++) acc[px][mt][nt][e] = 0.f;

    const int aRow0 = m0w + (lane & 15), aColSel = (lane >> 4);
    const int bRow0 = n0w + ((lane >> 4) << 3) + (lane & 7), bColSel = ((lane >> 3) & 1);

    for (int dyi = 0; dyi < 3; dyi++) {
        const int yy = y + dyi - 1;
        if (yy < 0 || yy >= 32) continue;        // uniform across CTA

        __syncthreads();   // prior-iteration reads complete before restage
        // Stage 6 B tiles: source pixels x0-1 .. x0+4, zero-filled when OOB.
#pragma unroll
        for (int bx = 0; bx < 6; bx++) {
            const int xx = x0 + bx - 1;
            char* dst = bP + bx * 16384;
            if (xx >= 0 && xx < 32) {
                const uint4* g = (const uint4*)spk + ((size_t)(yy * 32 + xx) * 256 + tbq * 64) * 16;
#pragma unroll
                for (int ps = 0; ps < 4; ps++) {
                    int vi = ps * 256 + tid;
                    *(uint4*)(dst + soff(vi >> 4, vi & 15)) = __ldg(&g[vi]);
                }
            } else {
#pragma unroll
                for (int ps = 0; ps < 4; ps++) {
                    int vi = ps * 256 + tid;
                    *(uint4*)(dst + soff(vi >> 4, vi & 15)) = make_uint4(0, 0, 0, 0);
                }
            }
        }
        // Stage 3 A tiles (taps of this dy-row), single fp16 split.
#pragma unroll
        for (int dxi = 0; dxi < 3; dxi++) {
            const uint4* g = (const uint4*)wp + (size_t)(dyi * 3 + dxi) * 2048;
            char* dst = aP + dxi * 32768;
#pragma unroll
            for (int ps = 0; ps < 8; ps++) {
                int vi = ps * 256 + tid;
                *(uint4*)(dst + soff(vi >> 4, vi & 15)) = __ldg(&g[vi]);
            }
        }
        __syncthreads();

#pragma unroll
        for (int j = 0; j < 8; j++) {
            uint32_t a[3][2][4];
#pragma unroll
            for (int dxi = 0; dxi < 3; dxi++)
#pragma unroll
                for (int mt = 0; mt < 2; mt++)
                    ldsm4(a[dxi][mt], aBu + dxi * 32768
                                      + soff(aRow0 + mt * 16, 2 * j + aColSel));
#pragma unroll
            for (int bxt = 0; bxt < 6; bxt++) {
                uint32_t b[2][4];
#pragma unroll
                for (int q = 0; q < 2; q++)
                    ldsm4(b[q], bBu + bxt * 16384
                                + soff(bRow0 + q * 16, 2 * j + bColSel));
#pragma unroll
                for (int px = 0; px < 4; px++)
#pragma unroll
                    for (int dxi = 0; dxi < 3; dxi++)
                        if (px + dxi == bxt) {
#pragma unroll
                            for (int mt = 0; mt < 2; mt++)
#pragma unroll
                                for (int q = 0; q < 2; q++)
#pragma unroll
                                    for (int t = 0; t < 2; t++)
                                        mma16816(acc[px][mt][q * 2 + t], a[dxi][mt],
                                                 b[q][t * 2], b[q][t * 2 + 1]);
                        }
            }
        }
    }

    // Epilogue: BN + store.
    const int lr = lane >> 2, lc = (lane & 3) * 2;
    float iv[2][2], bv[2][2];
#pragma unroll
    for (int mt = 0; mt < 2; mt++)
#pragma unroll
        for (int h = 0; h < 2; h++) {
            int co = m0w + mt * 16 + h * 8 + lr;
            float z = gamma[co] / sqrtf(var[co] + EPS);
            iv[mt][h] = z;
            bv[mt][h] = beta[co] - mean[co] * z;
        }
    if (MODE == 0) {
#pragma unroll
        for (int px = 0; px < 4; px++) {
            float* bas = out + (((size_t)(y * 32 + x0 + px) * 256) + tbq * 64) * 128;
#pragma unroll
            for (int mt = 0; mt < 2; mt++) {
                const int co = m0w + mt * 16 + lr;
#pragma unroll
                for (int nt = 0; nt < 4; nt++) {
                    const int n = n0w + nt * 8 + lc;
                    float* o = bas + (size_t)n * 128 + co;
                    o[0]   = acc[px][mt][nt][0] * iv[mt][0] + bv[mt][0];
                    o[128] = acc[px][mt][nt][1] * iv[mt][0] + bv[mt][0];
                    o[8]   = acc[px][mt][nt][2] * iv[mt][1] + bv[mt][1];
                    o[136] = acc[px][mt][nt][3] * iv[mt][1] + bv[mt][1];
                }
            }
        }
    } else {
        // NCHW: out[(tb*128+co)*1024 + y*32 + x], float4 over px (x0 % 4 == 0).
        const int pbase = y * 32 + x0;
#pragma unroll
        for (int mt = 0; mt < 2; mt++) {
            const int co = m0w + mt * 16 + lr;
#pragma unroll
            for (int nt = 0; nt < 4; nt++) {
                const int n = tbq * 64 + n0w + nt * 8 + lc;
#pragma unroll
                for (int e = 0; e < 4; e++) {
                    const int cc = co + (e >> 1) * 8;
                    const int nn = n + (e & 1);
                    const float z = iv[mt][e >> 1], bb = bv[mt][e >> 1];
                    float4 v = make_float4(acc[0][mt][nt][e] * z + bb,
                                           acc[1][mt][nt][e] * z + bb,
                                           acc[2][mt][nt][e] * z + bb,
                                           acc[3][mt][nt][e] * z + bb);
                    *(float4*)(out + ((size_t)nn * 128 + cc) * 1024 + pbase) = v;
                }
            }
        }
    }
}

// ------------------------- pipeline -----------------------------------------
extern "C" void kernel_launch(void* const* d_in, const int* in_sizes, int n_in,
                              void* d_out, int out_size) {
    const float* x  = (const float*)d_in[0];
    const float* w1 = (const float*)d_in[1];
    const float* g1 = (const float*)d_in[2];
    const float* b1 = (const float*)d_in[3];
    const float* m1 = (const float*)d_in[4];
    const float* v1 = (const float*)d_in[5];
    const float* w2 = (const float*)d_in[6];
    const float* g2 = (const float*)d_in[7];
    const float* b2 = (const float*)d_in[8];
    const float* m2 = (const float*)d_in[9];
    const float* v2 = (const float*)d_in[10];
    float* out = (float*)d_out;

    __half *spk, *spk2, *w1p, *w2p; float *mid, *w1t;
    cudaGetSymbolAddress((void**)&spk,  g_spk);
    cudaGetSymbolAddress((void**)&spk2, g_spk2);
    cudaGetSymbolAddress((void**)&mid,  g_mid);
    cudaGetSymbolAddress((void**)&w1p,  g_w1p);
    cudaGetSymbolAddress((void**)&w2p,  g_w2p);
    cudaGetSymbolAddress((void**)&w1t,  g_w1t);

    cudaFuncSetAttribute(conv_mma_kernel<0>, cudaFuncAttributeMaxDynamicSharedMemorySize, SMEMC);
    cudaFuncSetAttribute(conv_mma_kernel<1>, cudaFuncAttributeMaxDynamicSharedMemorySize, SMEMC);

    const int WB = (9 * 128 * 128 + 255) / 256;
    dim3 cgrid(8, 32, 4);

    // Order chosen so conv_mma_kernel<0> is the 4th launch (ncu capture slot).
    wprep_kernel<true><<<WB, 256>>>(w1, w1p, w1t);
    wprep_kernel<false><<<WB, 256>>>(w2, w2p, nullptr);
    if1_kernel<<<dim3(32, 4, 32), 1024>>>(x, spk);
    conv_mma_kernel<0><<<cgrid, 256, SMEMC>>>(spk, w1p, g1, b1, m1, v1, mid);
    zero_flag_kernel<<<1, 32>>>();
    if2_flag_kernel<<<NELEM / 256, 256>>>(mid, spk2);
    fix_kernel<<<2048, 128>>>(spk, w1t, g1, b1, m1, v1, spk2);
    conv_mma_kernel<1><<<cgrid, 256, SMEMC>>>(spk2, w2p, g2, b2, m2, v2, out);
}